// round 8
// baseline (speedup 1.0000x reference)
#include <cuda_runtime.h>
#include <cuda_fp16.h>
#include <cstdint>

#define NS0 300000
#define ND0 50000
#define NE0 800000
#define NS1 50000
#define ND1 8192
#define NE1 131072
#define INF 256
#define HIDF 128
#define OUTF 128

// ---------------- static device scratch ----------------
// All zero-init counters contiguous -> one memset node.
#define OFF_DEGOUT0 0
#define OFF_DEGIN0  (NS0)
#define OFF_DEGOUT1 (NS0 + ND0)
#define OFF_DEGIN1  (NS0 + ND0 + NS1)
#define CNT_TOTAL   (NS0 + ND0 + NS1 + ND1)
__device__ int   g_counters[CNT_TOTAL];

__device__ int   g_rowptr0[ND0 + 1];
__device__ int   g_work0[ND0];
__device__ int2  g_csr0[NE0];
__device__ __half2 g_y[(size_t)NS0 * (HIDF / 2)];   // x @ W1, fp16, 76.8 MB
__device__ float g_h1[(size_t)ND0 * HIDF];          // layer-1 output, 25.6 MB

__device__ int   g_rowptr1[ND1 + 1];
__device__ int   g_work1[ND1];
__device__ int2  g_csr1[NE1];

// ---------------- helpers ----------------
__device__ __forceinline__ uint32_t f2tf32(float f) {
    uint32_t r;
    asm("cvt.rna.tf32.f32 %0, %1;" : "=r"(r) : "f"(f));
    return r;
}

__device__ __forceinline__ void mma_tf32(float d[4], const uint32_t a[4],
                                         const uint32_t b0, const uint32_t b1,
                                         const float c[4]) {
    asm volatile(
        "mma.sync.aligned.m16n8k8.row.col.f32.tf32.tf32.f32 "
        "{%0,%1,%2,%3}, {%4,%5,%6,%7}, {%8,%9}, {%10,%11,%12,%13};\n"
        : "=f"(d[0]), "=f"(d[1]), "=f"(d[2]), "=f"(d[3])
        : "r"(a[0]), "r"(a[1]), "r"(a[2]), "r"(a[3]),
          "r"(b0), "r"(b1),
          "f"(c[0]), "f"(c[1]), "f"(c[2]), "f"(c[3]));
}

// ---------------- preprocessing ----------------

__global__ void __launch_bounds__(256) k_degree(const int* __restrict__ src0,
                                                const int* __restrict__ dst0,
                                                const int* __restrict__ src1,
                                                const int* __restrict__ dst1) {
    int i = blockIdx.x * blockDim.x + threadIdx.x;
    if (i < NE0 / 2) {
        int2 s = ((const int2*)src0)[i];
        int2 d = ((const int2*)dst0)[i];
        atomicAdd(&g_counters[OFF_DEGOUT0 + s.x], 1);
        atomicAdd(&g_counters[OFF_DEGOUT0 + s.y], 1);
        atomicAdd(&g_counters[OFF_DEGIN0 + d.x], 1);
        atomicAdd(&g_counters[OFF_DEGIN0 + d.y], 1);
    }
    if (i < NE1 / 2) {
        int2 s = ((const int2*)src1)[i];
        int2 d = ((const int2*)dst1)[i];
        atomicAdd(&g_counters[OFF_DEGOUT1 + s.x], 1);
        atomicAdd(&g_counters[OFF_DEGOUT1 + s.y], 1);
        atomicAdd(&g_counters[OFF_DEGIN1 + d.x], 1);
        atomicAdd(&g_counters[OFF_DEGIN1 + d.y], 1);
    }
}

__device__ __forceinline__ void scan_body(const int* __restrict__ deg,
                                          int* __restrict__ rowptr,
                                          int* __restrict__ work, int n) {
    __shared__ int partial[1024];
    const int t = threadIdx.x;
    const int C = (n + 1023) / 1024;
    const int start = t * C;
    const int end = min(start + C, n);
    int s = 0;
    for (int i = start; i < end; i++) s += deg[i];
    partial[t] = s;
    __syncthreads();
    for (int off = 1; off < 1024; off <<= 1) {
        int v = partial[t];
        int add = (t >= off) ? partial[t - off] : 0;
        __syncthreads();
        partial[t] = v + add;
        __syncthreads();
    }
    int run = (t == 0) ? 0 : partial[t - 1];
    for (int i = start; i < end; i++) {
        rowptr[i] = run;
        work[i] = run;
        run += deg[i];
    }
    if (t == 0) rowptr[n] = partial[1023];
}

__global__ void k_scan_both() {
    if (blockIdx.x == 0) scan_body(&g_counters[OFF_DEGIN0], g_rowptr0, g_work0, ND0);
    else                 scan_body(&g_counters[OFF_DEGIN1], g_rowptr1, g_work1, ND1);
}

__global__ void __launch_bounds__(256) k_fill(const int* __restrict__ src0,
                                              const int* __restrict__ dst0,
                                              const float* __restrict__ ew0,
                                              const int* __restrict__ src1,
                                              const int* __restrict__ dst1,
                                              const float* __restrict__ ew1) {
    int i = blockIdx.x * blockDim.x + threadIdx.x;
    if (i < NE0 / 2) {
        int2   s = ((const int2*)src0)[i];
        int2   d = ((const int2*)dst0)[i];
        float2 w = ((const float2*)ew0)[i];
        int pos0 = atomicAdd(&g_work0[d.x], 1);
        int pos1 = atomicAdd(&g_work0[d.y], 1);
        float w0 = w.x * rsqrtf(fmaxf((float)g_counters[OFF_DEGOUT0 + s.x], 1.0f));
        float w1 = w.y * rsqrtf(fmaxf((float)g_counters[OFF_DEGOUT0 + s.y], 1.0f));
        g_csr0[pos0] = make_int2(s.x, __float_as_int(w0));
        g_csr0[pos1] = make_int2(s.y, __float_as_int(w1));
    }
    if (i < NE1 / 2) {
        int2   s = ((const int2*)src1)[i];
        int2   d = ((const int2*)dst1)[i];
        float2 w = ((const float2*)ew1)[i];
        int pos0 = atomicAdd(&g_work1[d.x], 1);
        int pos1 = atomicAdd(&g_work1[d.y], 1);
        float w0 = w.x * rsqrtf(fmaxf((float)g_counters[OFF_DEGOUT1 + s.x], 1.0f));
        float w1 = w.y * rsqrtf(fmaxf((float)g_counters[OFF_DEGOUT1 + s.y], 1.0f));
        g_csr1[pos0] = make_int2(s.x, __float_as_int(w0));
        g_csr1[pos1] = make_int2(s.y, __float_as_int(w1));
    }
}

// ---------------- pre-GEMM: y[NS0,128] fp16 = x[NS0,256] @ W1 ----------------
// 512 threads, 32-row tiles, TF32 tensor cores. Streaming loads of x.
__global__ void __launch_bounds__(512) k_pregemm(const float* __restrict__ x,
                                                 const float* __restrict__ W,
                                                 __half2* __restrict__ y) {
    constexpr int D = INF;
    constexpr int ASTRIDE = D + 4;
    constexpr int TPR = D / 4;           // 64 threads per row
    constexpr int ROWS_PAR = 512 / TPR;  // 8 rows in parallel
    extern __shared__ char smem_raw[];
    float*    Ash = (float*)smem_raw;                          // 32*ASTRIDE floats
    uint32_t* Wsh = (uint32_t*)(smem_raw + 32 * ASTRIDE * 4);  // 32*136 u32

    const int tid = threadIdx.x;
    const int base = blockIdx.x * 32;    // NS0 % 32 == 0

    // ---- Phase 1: streaming load of A tile ----
    {
        const int rgrp = tid / TPR;
        const int lanein = tid % TPR;
        const int c4 = lanein * 4;
#pragma unroll
        for (int rr = rgrp; rr < 32; rr += ROWS_PAR) {
            const int row = base + rr;
            float4 v = __ldg((const float4*)&x[(size_t)row * D + c4]);
            float* dst = &Ash[rr * ASTRIDE + c4];
            dst[0] = v.x; dst[1] = v.y; dst[2] = v.z; dst[3] = v.w;
        }
    }

    // ---- Phase 2: TF32 GEMM 32xD @ Dx128 ----
    const int lane = tid & 31;
    const int warp = tid >> 5;
    const int warpM = warp & 1;     // 2 along M
    const int warpN = warp >> 1;    // 8 along N

    float acc[2][4];
#pragma unroll
    for (int nt = 0; nt < 2; nt++)
#pragma unroll
        for (int i = 0; i < 4; i++) acc[nt][i] = 0.0f;

    for (int kc = 0; kc < D; kc += 32) {
        __syncthreads();
#pragma unroll
        for (int it = 0; it < 2; it++) {
            int kk = (tid >> 5) + it * 16;
            int n = (tid & 31) * 4;
            float4 v = *(const float4*)&W[(size_t)(kc + kk) * 128 + n];
            uint32_t* dst = &Wsh[kk * 136 + n];
            dst[0] = f2tf32(v.x); dst[1] = f2tf32(v.y);
            dst[2] = f2tf32(v.z); dst[3] = f2tf32(v.w);
        }
        __syncthreads();

#pragma unroll
        for (int k8 = 0; k8 < 4; k8++) {
            const int kb = k8 * 8;
            const int rA = warpM * 16 + (lane >> 2);
            const int cA = kc + kb + (lane & 3);
            uint32_t afr[4];
            afr[0] = f2tf32(Ash[rA * ASTRIDE + cA]);
            afr[1] = f2tf32(Ash[(rA + 8) * ASTRIDE + cA]);
            afr[2] = f2tf32(Ash[rA * ASTRIDE + cA + 4]);
            afr[3] = f2tf32(Ash[(rA + 8) * ASTRIDE + cA + 4]);
            const int kkB = kb + (lane & 3);
#pragma unroll
            for (int nt = 0; nt < 2; nt++) {
                const int n = warpN * 16 + nt * 8 + (lane >> 2);
                uint32_t b0 = Wsh[kkB * 136 + n];
                uint32_t b1 = Wsh[(kkB + 4) * 136 + n];
                mma_tf32(acc[nt], afr, b0, b1, acc[nt]);
            }
        }
    }

    // ---- Epilogue: fp16 store (no bias/relu here) ----
#pragma unroll
    for (int nt = 0; nt < 2; nt++) {
        int col = warpN * 16 + nt * 8 + (lane & 3) * 2;  // even
        int r0 = base + warpM * 16 + (lane >> 2);
        y[(size_t)r0 * 64 + (col >> 1)] = __floats2half2_rn(acc[nt][0], acc[nt][1]);
        int r1 = r0 + 8;
        y[(size_t)r1 * 64 + (col >> 1)] = __floats2half2_rn(acc[nt][2], acc[nt][3]);
    }
}

// ---------------- layer-1 gather: h1 = relu(gather(y)*indeg^-0.5 + b1) -------
// One warp per dst row; lane covers 4 output features (8 B of fp16 per edge).
__global__ void __launch_bounds__(256) k_gather1(const int* __restrict__ rowptr,
                                                 const int2* __restrict__ csr,
                                                 const __half2* __restrict__ y,
                                                 const int* __restrict__ indeg,
                                                 const float* __restrict__ bias,
                                                 float* __restrict__ h1) {
    const int wrow = (blockIdx.x * blockDim.x + threadIdx.x) >> 5;
    const int lane = threadIdx.x & 31;
    if (wrow >= ND0) return;

    const int beg = __ldg(&rowptr[wrow]);
    const int end = __ldg(&rowptr[wrow + 1]);
    float4 acc = make_float4(0.f, 0.f, 0.f, 0.f);
    int j = beg;
    for (; j + 8 <= end; j += 8) {
        int2 e[8];
#pragma unroll
        for (int u = 0; u < 8; u++) e[u] = __ldg(&csr[j + u]);
        uint2 raw[8];
#pragma unroll
        for (int u = 0; u < 8; u++)
            raw[u] = __ldg((const uint2*)(y + (size_t)e[u].x * 64 + lane * 2));
#pragma unroll
        for (int u = 0; u < 8; u++) {
            float w = __int_as_float(e[u].y);
            float2 f0 = __half22float2(*(const __half2*)&raw[u].x);
            float2 f1 = __half22float2(*(const __half2*)&raw[u].y);
            acc.x += w * f0.x; acc.y += w * f0.y;
            acc.z += w * f1.x; acc.w += w * f1.y;
        }
    }
    for (; j < end; j++) {
        int2 e = __ldg(&csr[j]);
        float w = __int_as_float(e.y);
        uint2 raw = __ldg((const uint2*)(y + (size_t)e.x * 64 + lane * 2));
        float2 f0 = __half22float2(*(const __half2*)&raw.x);
        float2 f1 = __half22float2(*(const __half2*)&raw.y);
        acc.x += w * f0.x; acc.y += w * f0.y;
        acc.z += w * f1.x; acc.w += w * f1.y;
    }

    const float sc = rsqrtf(fmaxf((float)__ldg(&indeg[wrow]), 1.0f));
    const float4 b = __ldg((const float4*)&bias[lane * 4]);
    float4 v;
    v.x = fmaxf(acc.x * sc + b.x, 0.0f);
    v.y = fmaxf(acc.y * sc + b.y, 0.0f);
    v.z = fmaxf(acc.z * sc + b.z, 0.0f);
    v.w = fmaxf(acc.w * sc + b.w, 0.0f);
    *(float4*)&h1[(size_t)wrow * HIDF + lane * 4] = v;
}

// ---------------- fused aggregate + TF32 GEMM (layer 2) ----------------
template <int D>
__global__ void __launch_bounds__(512) k_fused(const int* __restrict__ rowptr,
                                               const int2* __restrict__ csr,
                                               const float* __restrict__ feat,
                                               const int* __restrict__ indeg,
                                               const float* __restrict__ W,
                                               const float* __restrict__ bias,
                                               float* __restrict__ out,
                                               int nrows) {
    constexpr int ASTRIDE = D + 4;
    constexpr int TPR = D / 4;
    constexpr int ROWS_PAR = 512 / TPR;
    extern __shared__ char smem_raw[];
    float*    Ash = (float*)smem_raw;
    uint32_t* Wsh = (uint32_t*)(smem_raw + 32 * ASTRIDE * 4);

    const int tid = threadIdx.x;
    const int base = blockIdx.x * 32;

    // ---- Phase 1: gather ----
    {
        const int rgrp = tid / TPR;
        const int lanein = tid % TPR;
        const int c4 = lanein * 4;
#pragma unroll
        for (int rr = rgrp; rr < 32; rr += ROWS_PAR) {
            const int row = base + rr;
            float4 acc = make_float4(0.f, 0.f, 0.f, 0.f);
            if (row < nrows) {
                const int beg = __ldg(&rowptr[row]);
                const int end = __ldg(&rowptr[row + 1]);
                int j = beg;
                for (; j + 8 <= end; j += 8) {
                    int2 e[8];
#pragma unroll
                    for (int u = 0; u < 8; u++) e[u] = __ldg(&csr[j + u]);
                    float4 f[8];
#pragma unroll
                    for (int u = 0; u < 8; u++)
                        f[u] = __ldg((const float4*)&feat[(size_t)e[u].x * D + c4]);
#pragma unroll
                    for (int u = 0; u < 8; u++) {
                        float wv = __int_as_float(e[u].y);
                        acc.x += wv * f[u].x;
                        acc.y += wv * f[u].y;
                        acc.z += wv * f[u].z;
                        acc.w += wv * f[u].w;
                    }
                }
                for (; j < end; j++) {
                    int2 e = __ldg(&csr[j]);
                    float wv = __int_as_float(e.y);
                    float4 f = __ldg((const float4*)&feat[(size_t)e.x * D + c4]);
                    acc.x += wv * f.x; acc.y += wv * f.y;
                    acc.z += wv * f.z; acc.w += wv * f.w;
                }
                float sc = rsqrtf(fmaxf((float)__ldg(&indeg[row]), 1.0f));
                acc.x *= sc; acc.y *= sc; acc.z *= sc; acc.w *= sc;
            }
            float* dst = &Ash[rr * ASTRIDE + c4];
            dst[0] = acc.x; dst[1] = acc.y; dst[2] = acc.z; dst[3] = acc.w;
        }
    }

    // ---- Phase 2: TF32 GEMM 32xD @ Dx128 ----
    const int lane = tid & 31;
    const int warp = tid >> 5;
    const int warpM = warp & 1;
    const int warpN = warp >> 1;

    float acc[2][4];
#pragma unroll
    for (int nt = 0; nt < 2; nt++)
#pragma unroll
        for (int i = 0; i < 4; i++) acc[nt][i] = 0.0f;

    for (int kc = 0; kc < D; kc += 32) {
        __syncthreads();
#pragma unroll
        for (int it = 0; it < 2; it++) {
            int kk = (tid >> 5) + it * 16;
            int n = (tid & 31) * 4;
            float4 v = *(const float4*)&W[(size_t)(kc + kk) * 128 + n];
            uint32_t* dst = &Wsh[kk * 136 + n];
            dst[0] = f2tf32(v.x); dst[1] = f2tf32(v.y);
            dst[2] = f2tf32(v.z); dst[3] = f2tf32(v.w);
        }
        __syncthreads();

#pragma unroll
        for (int k8 = 0; k8 < 4; k8++) {
            const int kb = k8 * 8;
            const int rA = warpM * 16 + (lane >> 2);
            const int cA = kc + kb + (lane & 3);
            uint32_t afr[4];
            afr[0] = f2tf32(Ash[rA * ASTRIDE + cA]);
            afr[1] = f2tf32(Ash[(rA + 8) * ASTRIDE + cA]);
            afr[2] = f2tf32(Ash[rA * ASTRIDE + cA + 4]);
            afr[3] = f2tf32(Ash[(rA + 8) * ASTRIDE + cA + 4]);
            const int kkB = kb + (lane & 3);
#pragma unroll
            for (int nt = 0; nt < 2; nt++) {
                const int n = warpN * 16 + nt * 8 + (lane >> 2);
                uint32_t b0 = Wsh[kkB * 136 + n];
                uint32_t b1 = Wsh[(kkB + 4) * 136 + n];
                mma_tf32(acc[nt], afr, b0, b1, acc[nt]);
            }
        }
    }

    // ---- Epilogue: bias + relu ----
#pragma unroll
    for (int nt = 0; nt < 2; nt++) {
        int col = warpN * 16 + nt * 8 + (lane & 3) * 2;
        float bb0 = __ldg(&bias[col]);
        float bb1 = __ldg(&bias[col + 1]);
        int r0 = base + warpM * 16 + (lane >> 2);
        if (r0 < nrows) {
            float2 v;
            v.x = fmaxf(acc[nt][0] + bb0, 0.0f);
            v.y = fmaxf(acc[nt][1] + bb1, 0.0f);
            *(float2*)&out[(size_t)r0 * 128 + col] = v;
        }
        int r1 = r0 + 8;
        if (r1 < nrows) {
            float2 v;
            v.x = fmaxf(acc[nt][2] + bb0, 0.0f);
            v.y = fmaxf(acc[nt][3] + bb1, 0.0f);
            *(float2*)&out[(size_t)r1 * 128 + col] = v;
        }
    }
}

// ---------------- launch ----------------
extern "C" void kernel_launch(void* const* d_in, const int* in_sizes, int n_in,
                              void* d_out, int out_size) {
    const float* x    = (const float*)d_in[0];
    const int*   src0 = (const int*)d_in[1];
    const int*   dst0 = (const int*)d_in[2];
    const float* ew0  = (const float*)d_in[3];
    const int*   src1 = (const int*)d_in[4];
    const int*   dst1 = (const int*)d_in[5];
    const float* ew1  = (const float*)d_in[6];
    const float* W1   = (const float*)d_in[7];
    const float* b1   = (const float*)d_in[8];
    const float* W2   = (const float*)d_in[9];
    const float* b2   = (const float*)d_in[10];
    float* out = (float*)d_out;

    int *counters, *rowptr0, *rowptr1;
    int2 *csr0, *csr1;
    float *h1;
    __half2 *y;
    cudaGetSymbolAddress((void**)&counters, g_counters);
    cudaGetSymbolAddress((void**)&rowptr0,  g_rowptr0);
    cudaGetSymbolAddress((void**)&csr0,     g_csr0);
    cudaGetSymbolAddress((void**)&rowptr1,  g_rowptr1);
    cudaGetSymbolAddress((void**)&csr1,     g_csr1);
    cudaGetSymbolAddress((void**)&h1,       g_h1);
    cudaGetSymbolAddress((void**)&y,        g_y);

    const int* indeg0 = counters + OFF_DEGIN0;
    const int* indeg1 = counters + OFF_DEGIN1;

    const int smem_pre = (32 * (INF + 4)) * 4 + 32 * 136 * 4;    // 50688
    const int smem2    = (32 * (HIDF + 4)) * 4 + 32 * 136 * 4;   // 34304
    cudaFuncSetAttribute(k_pregemm,     cudaFuncAttributeMaxDynamicSharedMemorySize, smem_pre);
    cudaFuncSetAttribute(k_fused<HIDF>, cudaFuncAttributeMaxDynamicSharedMemorySize, smem2);

    cudaMemsetAsync(counters, 0, CNT_TOTAL * sizeof(int), 0);

    k_degree<<<(NE0 / 2 + 255) / 256, 256>>>(src0, dst0, src1, dst1);
    k_scan_both<<<2, 1024>>>();
    k_fill<<<(NE0 / 2 + 255) / 256, 256>>>(src0, dst0, ew0, src1, dst1, ew1);
    k_pregemm<<<NS0 / 32, 512, smem_pre>>>(x, W1, y);
    k_gather1<<<(ND0 * 32 + 255) / 256, 256>>>(rowptr0, csr0, y, indeg0, b1, h1);
    k_fused<HIDF><<<(ND1 + 31) / 32, 512, smem2>>>(rowptr1, csr1, h1,
                                                   indeg1, W2, b2, out, ND1);
}